// round 6
// baseline (speedup 1.0000x reference)
#include <cuda_runtime.h>
#include <cstdint>
#include <cstddef>

typedef unsigned long long ull;

#define S_LEN   2048
#define BATCH   32
#define HID     256
#define GRID_REC 128

// ---------------- device scratch (no allocations allowed) ----------------
__device__ float g_Xc[(size_t)65536 * 1024];   // [s][b][col] : 256 MB, x@Wx + b
__device__ float g_hbuf[2][BATCH * HID];       // k-PAIR layout: [k2][b][2], double buffered
__device__ unsigned g_flags[GRID_REC];         // distributed barrier flags (per-CTA epoch)

// ---------------- activations (accurate fast paths) ----------------
__device__ __forceinline__ float fsigm(float x) {
    return 1.0f / (1.0f + __expf(-x));
}
__device__ __forceinline__ float ftanh(float x) {
    x = fminf(9.0f, fmaxf(-9.0f, x));
    float e = __expf(-2.0f * x);
    return __fdividef(1.0f - e, 1.0f + e);
}

// ---------------- packed fp32x2 helpers ----------------
__device__ __forceinline__ ull ffma2(ull a, ull b, ull c) {
    ull d;
    asm("fma.rn.f32x2 %0, %1, %2, %3;" : "=l"(d) : "l"(a), "l"(b), "l"(c));
    return d;
}
__device__ __forceinline__ float f2sum(ull v) {
    float lo = __uint_as_float((unsigned)(v & 0xffffffffull));
    float hi = __uint_as_float((unsigned)(v >> 32));
    return lo + hi;
}
__device__ __forceinline__ ull fpack(float lo, float hi) {
    return ((ull)__float_as_uint(hi) << 32) | (ull)__float_as_uint(lo);
}

// ---------------- phase 1: Xc[s][b][col] = x[b][s][:] @ W[:256][col] + bias[col] ----------------
// M = 65536 rows ordered r = s*32 + b ; N = 1024 ; K = 256
__global__ void __launch_bounds__(256) gemm_x_kernel(const float* __restrict__ x,
                                                     const float* __restrict__ W,
                                                     const float* __restrict__ bias) {
    __shared__ float As[8][132];   // k-major, padded (conflict-free)
    __shared__ float Bs[8][128];
    const int tid = threadIdx.x;
    const int rt = blockIdx.x, ct = blockIdx.y;

    const int a_ri = tid >> 1, a_kq = (tid & 1) << 2;
    const int row  = rt * 128 + a_ri;            // r = s*32 + b
    const float* a_src = x + (size_t)(row & 31) * (S_LEN * 256)
                           + (size_t)(row >> 5) * 256 + a_kq;
    const int b_kr = tid >> 5, b_c4 = (tid & 31) << 2;
    const float* b_src = W + (size_t)b_kr * 1024 + ct * 128 + b_c4;

    const int ry = tid >> 4, cx = tid & 15;
    float acc[8][8];
#pragma unroll
    for (int i = 0; i < 8; i++)
#pragma unroll
        for (int j = 0; j < 8; j++) acc[i][j] = 0.0f;

    for (int kb = 0; kb < 256; kb += 8) {
        float4 av = *(const float4*)(a_src + kb);
        float4 bv = *(const float4*)(b_src + (size_t)kb * 1024);
        __syncthreads();
        As[a_kq + 0][a_ri] = av.x;
        As[a_kq + 1][a_ri] = av.y;
        As[a_kq + 2][a_ri] = av.z;
        As[a_kq + 3][a_ri] = av.w;
        *(float4*)&Bs[b_kr][b_c4] = bv;
        __syncthreads();
#pragma unroll
        for (int k = 0; k < 8; k++) {
            float ar[8], br[8];
            *(float4*)(ar)     = *(const float4*)&As[k][ry * 8];
            *(float4*)(ar + 4) = *(const float4*)&As[k][ry * 8 + 4];
            *(float4*)(br)     = *(const float4*)&Bs[k][cx * 8];
            *(float4*)(br + 4) = *(const float4*)&Bs[k][cx * 8 + 4];
#pragma unroll
            for (int i = 0; i < 8; i++)
#pragma unroll
                for (int j = 0; j < 8; j++)
                    acc[i][j] = fmaf(ar[i], br[j], acc[i][j]);
        }
    }

    float bb[8];
#pragma unroll
    for (int j = 0; j < 8; j++) bb[j] = bias[ct * 128 + cx * 8 + j];

    // coalesced epilogue: [s][b][col] layout -> row-major [r][col], float4 stores
#pragma unroll
    for (int i = 0; i < 8; i++) {
        int r = rt * 128 + ry * 8 + i;
        float* dst = g_Xc + (size_t)r * 1024 + ct * 128 + cx * 8;
        float4 v0, v1;
        v0.x = acc[i][0] + bb[0]; v0.y = acc[i][1] + bb[1];
        v0.z = acc[i][2] + bb[2]; v0.w = acc[i][3] + bb[3];
        v1.x = acc[i][4] + bb[4]; v1.y = acc[i][5] + bb[5];
        v1.z = acc[i][6] + bb[6]; v1.w = acc[i][7] + bb[7];
        *(float4*)dst = v0;
        *(float4*)(dst + 4) = v1;
    }
}

// ---------------- init: flags reset, h0 transpose into k-pair layout, zero output tail ----------------
__global__ void init_kernel(const float* __restrict__ h0, float* __restrict__ out) {
    int t = blockIdx.x * blockDim.x + threadIdx.x;   // 16*256 = 4096 threads
    if (t < GRID_REC) g_flags[t] = 0;
    for (int idx = t; idx < BATCH * HID; idx += 4096) {
        int k = idx >> 5, b = idx & 31;
        // layout: [k2][b][2] with k2 = k>>1
        g_hbuf[0][(k >> 1) * 64 + b * 2 + (k & 1)] = h0[b * HID + k];
    }
    float* tail = out + (size_t)BATCH * S_LEN * HID;            // the two zero tensors
    for (int idx = t; idx < 2 * BATCH * HID; idx += 4096) tail[idx] = 0.0f;
}

// ---------------- grid-wide barrier: distributed flags, NO atomic serialization ----------------
// Each CTA releases its own flag; threads 0..127 each acquire-poll one flag in parallel.
__device__ __forceinline__ void grid_barrier(int cb, int step) {
    __syncthreads();
    if (threadIdx.x == 0) {
        asm volatile("st.release.gpu.global.u32 [%0], %1;"
                     :: "l"(&g_flags[cb]), "r"((unsigned)(step + 1)) : "memory");
    }
    if (threadIdx.x < GRID_REC) {
        unsigned e;
        do {
            asm volatile("ld.acquire.gpu.global.u32 %0, [%1];"
                         : "=r"(e) : "l"(&g_flags[threadIdx.x]) : "memory");
        } while (e < (unsigned)(step + 1));
    }
    __syncthreads();
}

// ---------------- phase 2: persistent recurrence ----------------
// CTA cb owns hidden units n in {2cb, 2cb+1} for all 32 batches.
// Dot-product: thread t: b = t&31, slot = t>>5 -> (nl = slot&1, ks = slot>>1), kseg = 64 k (32 k-pairs).
// f32x2 FFMA2 over k-pairs; smem reduce; stage-2: all 256 threads assemble z + activations;
// stage-3: 64 owner threads update c,h.
__global__ void __launch_bounds__(256, 1) lstm_rec_kernel(const float* __restrict__ W,
                                                          const float* __restrict__ c0,
                                                          float* __restrict__ out) {
    __shared__ ull  h2s[128 * 32];         // h, k-pair layout [k2][b] as f32x2 : 32 KB
    __shared__ ull  Wsh2[8 * 128];         // [ (nl*4+g) ][k2] as f32x2 : 8 KB (weight-stationary)
    __shared__ float red[4][2][4][32];     // [ks][nl][gate][b]  4 KB
    __shared__ float act_s[2][4][32];      // [nl][gate][b]      1 KB

    const int tid = threadIdx.x;
    const int cb = blockIdx.x;
    const int n_base = cb * 2;

    // one-time Wh load: Wsh2[nl*4+g][k2] = (W[256+2k2][col], W[256+2k2+1][col])
    for (int idx = tid; idx < 1024; idx += 256) {
        int cl = idx >> 7, k2 = idx & 127;
        int col = (cl & 3) * 256 + n_base + (cl >> 2);
        float wlo = W[(size_t)(256 + 2 * k2) * 1024 + col];
        float whi = W[(size_t)(257 + 2 * k2) * 1024 + col];
        Wsh2[cl * 128 + k2] = fpack(wlo, whi);
    }

    // dot-product mapping
    const int b    = tid & 31;
    const int slot = tid >> 5;
    const int nl   = slot & 1;
    const int ks   = slot >> 1;       // 0..3, kseg of 32 k-pairs

    // stage-2 mapping: one (nl2, g2, b2) per thread
    const int b2  = tid & 31;
    const int nl2 = (tid >> 5) & 1;
    const int g2  = tid >> 6;
    const int xcol = g2 * 256 + n_base + nl2;

    // owner mapping (c/h update): 64 threads = 2 nl x 32 b
    const bool owner = (tid < 64);
    const int o_b  = tid & 31;
    const int o_nl = (tid >> 5) & 1;
    const int o_n  = n_base + o_nl;
    float c_reg = 0.0f;
    if (owner) c_reg = c0[o_b * HID + o_n];

    const ull* hseg = h2s + (ks * 32) * 32 + b;
    const ulonglong2* w0p = (const ulonglong2*)(Wsh2 + (nl * 4 + 0) * 128 + ks * 32);
    const ulonglong2* w1p = (const ulonglong2*)(Wsh2 + (nl * 4 + 1) * 128 + ks * 32);
    const ulonglong2* w2p = (const ulonglong2*)(Wsh2 + (nl * 4 + 2) * 128 + ks * 32);
    const ulonglong2* w3p = (const ulonglong2*)(Wsh2 + (nl * 4 + 3) * 128 + ks * 32);

    // prefetch Xc for step 0 : layout [s][b][col]
    float xc_cur = g_Xc[(size_t)b2 * 1024 + xcol];
    __syncthreads();

    for (int s = 0; s < S_LEN; s++) {
        // load h into smem (coalesced float4 copy; layouts identical)
        {
            float4* d4 = (float4*)h2s;
            const float4* s4 = (const float4*)g_hbuf[s & 1];
#pragma unroll
            for (int j = 0; j < 8; j++) d4[tid + 256 * j] = s4[tid + 256 * j];
        }
        __syncthreads();

        // 4 gate dot-products over this thread's 32 k-pairs (FFMA2)
        ull a0 = 0ull, a1 = 0ull, a2 = 0ull, a3 = 0ull;
#pragma unroll
        for (int j = 0; j < 16; j++) {
            ull hA = hseg[(2 * j) * 32];        // LDS.64, conflict-free
            ull hB = hseg[(2 * j + 1) * 32];
            ulonglong2 w0 = w0p[j];             // LDS.128 broadcast
            ulonglong2 w1 = w1p[j];
            ulonglong2 w2 = w2p[j];
            ulonglong2 w3 = w3p[j];
            a0 = ffma2(hA, w0.x, a0); a0 = ffma2(hB, w0.y, a0);
            a1 = ffma2(hA, w1.x, a1); a1 = ffma2(hB, w1.y, a1);
            a2 = ffma2(hA, w2.x, a2); a2 = ffma2(hB, w2.y, a2);
            a3 = ffma2(hA, w3.x, a3); a3 = ffma2(hB, w3.y, a3);
        }
        red[ks][nl][0][b] = f2sum(a0);
        red[ks][nl][1][b] = f2sum(a1);
        red[ks][nl][2][b] = f2sum(a2);
        red[ks][nl][3][b] = f2sum(a3);
        __syncthreads();

        // stage 2: every thread assembles one z and applies activations
        {
            float z = red[0][nl2][g2][b2] + red[1][nl2][g2][b2]
                    + red[2][nl2][g2][b2] + red[3][nl2][g2][b2] + xc_cur;
            z = ftanh(z);                                    // reference quirk: tanh first
            float a = (g2 == 2) ? ftanh(z) : fsigm(z);
            act_s[nl2][g2][b2] = a;
        }
        __syncthreads();

        // stage 3: owners update cell + hidden
        if (owner) {
            float iv = act_s[o_nl][0][o_b];
            float fv = act_s[o_nl][1][o_b];
            float gv = act_s[o_nl][2][o_b];
            float ov = act_s[o_nl][3][o_b];
            c_reg = fv * c_reg + iv * gv;
            float hv = ftanh(c_reg) * ov;
            g_hbuf[(s & 1) ^ 1][cb * 64 + o_b * 2 + o_nl] = hv;   // k-pair layout
            out[(size_t)o_b * (S_LEN * HID) + (size_t)s * HID + o_n] = hv;
        }

        // prefetch next step's Xc BEFORE the barrier (DRAM latency hidden under the wait)
        if (s + 1 < S_LEN)
            xc_cur = g_Xc[(size_t)(s + 1) * 32768 + (size_t)b2 * 1024 + xcol];

        grid_barrier(cb, s);
    }
}

// ---------------- launch ----------------
extern "C" void kernel_launch(void* const* d_in, const int* in_sizes, int n_in,
                              void* d_out, int out_size) {
    const float* x    = (const float*)d_in[0];   // (32,2048,256)
    const float* h0   = (const float*)d_in[1];   // (1,32,256)
    const float* c0   = (const float*)d_in[2];   // (1,32,256)
    const float* W    = (const float*)d_in[3];   // (512,1024)
    const float* bias = (const float*)d_in[4];   // (1024,)
    float* out = (float*)d_out;                  // (32,2048,256) + 2*(1,32,256) zeros

    gemm_x_kernel<<<dim3(512, 8, 1), 256>>>(x, W, bias);
    init_kernel<<<16, 256>>>(h0, out);
    lstm_rec_kernel<<<GRID_REC, 256>>>(W, c0, out);
}

// round 7
// speedup vs baseline: 1.5503x; 1.5503x over previous
#include <cuda_runtime.h>
#include <cstdint>
#include <cstddef>

typedef unsigned long long ull;

#define S_LEN    2048
#define BATCH    32
#define HID      256
#define CLUSTER  8
#define N_CLUST  16
#define GRID_REC (CLUSTER * N_CLUST)   // 128

// ---------------- device scratch (no allocations allowed) ----------------
__device__ float g_Xc[(size_t)65536 * 1024];   // [s][b][col] : 256 MB, x@Wx + b

// ---------------- activations (accurate fast paths) ----------------
__device__ __forceinline__ float fsigm(float x) {
    return 1.0f / (1.0f + __expf(-x));
}
__device__ __forceinline__ float ftanh(float x) {
    x = fminf(9.0f, fmaxf(-9.0f, x));
    float e = __expf(-2.0f * x);
    return __fdividef(1.0f - e, 1.0f + e);
}

// ---------------- packed fp32x2 helpers ----------------
__device__ __forceinline__ ull ffma2(ull a, ull b, ull c) {
    ull d;
    asm("fma.rn.f32x2 %0, %1, %2, %3;" : "=l"(d) : "l"(a), "l"(b), "l"(c));
    return d;
}
__device__ __forceinline__ float f2sum(ull v) {
    float lo = __uint_as_float((unsigned)(v & 0xffffffffull));
    float hi = __uint_as_float((unsigned)(v >> 32));
    return lo + hi;
}
__device__ __forceinline__ ull fpack(float lo, float hi) {
    return ((ull)__float_as_uint(hi) << 32) | (ull)__float_as_uint(lo);
}

// ---------------- phase 1: Xc[s][b][col] = x[b][s][:] @ W[:256][col] + bias[col] ----------------
// M = 65536 rows ordered r = s*32 + b ; N = 1024 ; K = 256
__global__ void __launch_bounds__(256) gemm_x_kernel(const float* __restrict__ x,
                                                     const float* __restrict__ W,
                                                     const float* __restrict__ bias) {
    __shared__ float As[8][132];   // k-major, padded (conflict-free)
    __shared__ float Bs[8][128];
    const int tid = threadIdx.x;
    const int rt = blockIdx.x, ct = blockIdx.y;

    const int a_ri = tid >> 1, a_kq = (tid & 1) << 2;
    const int row  = rt * 128 + a_ri;            // r = s*32 + b
    const float* a_src = x + (size_t)(row & 31) * (S_LEN * 256)
                           + (size_t)(row >> 5) * 256 + a_kq;
    const int b_kr = tid >> 5, b_c4 = (tid & 31) << 2;
    const float* b_src = W + (size_t)b_kr * 1024 + ct * 128 + b_c4;

    const int ry = tid >> 4, cx = tid & 15;
    float acc[8][8];
#pragma unroll
    for (int i = 0; i < 8; i++)
#pragma unroll
        for (int j = 0; j < 8; j++) acc[i][j] = 0.0f;

    for (int kb = 0; kb < 256; kb += 8) {
        float4 av = *(const float4*)(a_src + kb);
        float4 bv = *(const float4*)(b_src + (size_t)kb * 1024);
        __syncthreads();
        As[a_kq + 0][a_ri] = av.x;
        As[a_kq + 1][a_ri] = av.y;
        As[a_kq + 2][a_ri] = av.z;
        As[a_kq + 3][a_ri] = av.w;
        *(float4*)&Bs[b_kr][b_c4] = bv;
        __syncthreads();
#pragma unroll
        for (int k = 0; k < 8; k++) {
            float ar[8], br[8];
            *(float4*)(ar)     = *(const float4*)&As[k][ry * 8];
            *(float4*)(ar + 4) = *(const float4*)&As[k][ry * 8 + 4];
            *(float4*)(br)     = *(const float4*)&Bs[k][cx * 8];
            *(float4*)(br + 4) = *(const float4*)&Bs[k][cx * 8 + 4];
#pragma unroll
            for (int i = 0; i < 8; i++)
#pragma unroll
                for (int j = 0; j < 8; j++)
                    acc[i][j] = fmaf(ar[i], br[j], acc[i][j]);
        }
    }

    float bb[8];
#pragma unroll
    for (int j = 0; j < 8; j++) bb[j] = bias[ct * 128 + cx * 8 + j];

    // coalesced epilogue: [s][b][col] layout -> row-major [r][col], float4 stores
#pragma unroll
    for (int i = 0; i < 8; i++) {
        int r = rt * 128 + ry * 8 + i;
        float* dst = g_Xc + (size_t)r * 1024 + ct * 128 + cx * 8;
        float4 v0, v1;
        v0.x = acc[i][0] + bb[0]; v0.y = acc[i][1] + bb[1];
        v0.z = acc[i][2] + bb[2]; v0.w = acc[i][3] + bb[3];
        v1.x = acc[i][4] + bb[4]; v1.y = acc[i][5] + bb[5];
        v1.z = acc[i][6] + bb[6]; v1.w = acc[i][7] + bb[7];
        *(float4*)dst = v0;
        *(float4*)(dst + 4) = v1;
    }
}

// ---------------- init: zero the two tail tensors of the output ----------------
__global__ void init_kernel(float* __restrict__ out) {
    int t = blockIdx.x * blockDim.x + threadIdx.x;   // 4096 threads
    float* tail = out + (size_t)BATCH * S_LEN * HID;
    for (int idx = t; idx < 2 * BATCH * HID; idx += 4096) tail[idx] = 0.0f;
}

// ---------------- phase 2: cluster-local recurrence ----------------
// 16 clusters x 8 CTAs. Cluster cl owns batches {2cl, 2cl+1}. CTA rank owns
// hidden units n in [32*rank, 32*rank+32) -> 128 gate-cols, weights REGISTER-
// resident (128 f32/thread). h (both batches, full 256) lives in smem, double
// buffered; new h exchanged via DSMEM stores + barrier.cluster each step.
__global__ void __launch_bounds__(256, 1) __cluster_dims__(CLUSTER, 1, 1)
lstm_rec_kernel(const float* __restrict__ W,
                const float* __restrict__ h0,
                const float* __restrict__ c0,
                float* __restrict__ out) {
    __shared__ __align__(16) ull h2s[2][128][2];   // [buf][k2][b] : 4 KB
    __shared__ float red[2][128][2];               // [kh][c][b]   : 2 KB
    __shared__ float act_s[128][2];                // [c][b]       : 1 KB

    const int tid  = threadIdx.x;
    const int cb   = blockIdx.x;
    const int rank = cb & (CLUSTER - 1);
    const int cl   = cb >> 3;
    const int b0g  = cl * 2;                       // first global batch of this cluster

    // ---- dot mapping: c = local col (0..127), kh = k-half (0/1) ----
    const int c   = tid & 127;
    const int kh  = tid >> 7;                      // uniform per warp
    const int g   = c >> 5;
    const int n   = rank * 32 + (c & 31);
    const int colg = g * 256 + n;

    // ---- register-resident Wh slice: 64 k-pairs for (colg, kh) ----
    ull w[64];
#pragma unroll
    for (int j = 0; j < 64; j++) {
        int k = 256 + kh * 128 + 2 * j;
        w[j] = fpack(W[(size_t)k * 1024 + colg],
                     W[(size_t)(k + 1) * 1024 + colg]);
    }

    // ---- stage-2 mapping (z assembly + activation): (c2, bl2) ----
    const int c2  = tid & 127;
    const int bl2 = tid >> 7;
    const int g2  = c2 >> 5;
    const int n2  = rank * 32 + (c2 & 31);
    const int col2 = g2 * 256 + n2;
    const int bg2  = b0g + bl2;

    // ---- owner mapping (c/h update): 64 threads = 32 n x 2 b ----
    const bool owner = (tid < 64);
    const int o_nl = tid & 31;
    const int o_bl = (tid >> 5) & 1;
    const int o_n  = rank * 32 + o_nl;
    const int o_bg = b0g + o_bl;
    float c_reg = owner ? c0[o_bg * HID + o_n] : 0.0f;

    // ---- precompute peer h2s addresses (DSMEM) for owners ----
    uint32_t hbase = (uint32_t)__cvta_generic_to_shared(&h2s[0][0][0]);
    uint32_t peer[CLUSTER];
    const uint32_t fixed_off = (uint32_t)((o_n >> 1) * 16 + o_bl * 8 + (o_n & 1) * 4);
#pragma unroll
    for (int r = 0; r < CLUSTER; r++) {
        uint32_t ra;
        asm("mapa.shared::cluster.u32 %0, %1, %2;" : "=r"(ra) : "r"(hbase), "r"(r));
        peer[r] = ra + fixed_off;
    }

    // ---- init h2s buf0 (full h, both batches) from h0 ----
    {
        int k2 = tid >> 1, bb = tid & 1;           // 256 entries, one per thread
        h2s[0][k2][bb] = fpack(h0[(b0g + bb) * HID + 2 * k2],
                               h0[(b0g + bb) * HID + 2 * k2 + 1]);
    }

    // prefetch Xc for step 0 : layout [s][b][col]
    float xc_cur = g_Xc[(size_t)bg2 * 1024 + col2];

    asm volatile("barrier.cluster.arrive.aligned;" ::: "memory");
    asm volatile("barrier.cluster.wait.aligned;" ::: "memory");

    for (int s = 0; s < S_LEN; s++) {
        // ---- dots: 128 k-pairs, weights in regs, h broadcast LDS.128 ----
        const ulonglong2* hptr = (const ulonglong2*)&h2s[s & 1][kh * 64][0];
        ull acc0 = 0ull, acc1 = 0ull;
#pragma unroll
        for (int j = 0; j < 64; j++) {
            ulonglong2 hv = hptr[j];               // [b0 pair, b1 pair] : uniform addr
            acc0 = ffma2(w[j], hv.x, acc0);
            acc1 = ffma2(w[j], hv.y, acc1);
        }
        red[kh][c][0] = f2sum(acc0);
        red[kh][c][1] = f2sum(acc1);
        __syncthreads();

        // ---- stage 2: z assembly + activations, one (col,b) per thread ----
        {
            float z = red[0][c2][bl2] + red[1][c2][bl2] + xc_cur;
            z = ftanh(z);                          // reference quirk: tanh first
            act_s[c2][bl2] = (g2 == 2) ? ftanh(z) : fsigm(z);
        }
        __syncthreads();

        // ---- stage 3: owners update c,h ; broadcast h to all 8 CTAs ----
        if (owner) {
            float iv = act_s[0 * 32 + o_nl][o_bl];
            float fv = act_s[1 * 32 + o_nl][o_bl];
            float gv = act_s[2 * 32 + o_nl][o_bl];
            float ov = act_s[3 * 32 + o_nl][o_bl];
            c_reg = fv * c_reg + iv * gv;
            float hv = ftanh(c_reg) * ov;
            uint32_t boff = (uint32_t)(((s & 1) ^ 1) * sizeof(h2s[0]));
#pragma unroll
            for (int r = 0; r < CLUSTER; r++)
                asm volatile("st.shared::cluster.f32 [%0], %1;"
                             :: "r"(peer[r] + boff), "f"(hv) : "memory");
            out[(size_t)o_bg * (S_LEN * HID) + (size_t)s * HID + o_n] = hv;
        }

        // arrive (release covers the DSMEM stores), hide Xc prefetch, then wait
        asm volatile("barrier.cluster.arrive.aligned;" ::: "memory");
        if (s + 1 < S_LEN)
            xc_cur = g_Xc[(size_t)(s + 1) * 32768 + (size_t)bg2 * 1024 + col2];
        asm volatile("barrier.cluster.wait.aligned;" ::: "memory");
    }
}

// ---------------- launch ----------------
extern "C" void kernel_launch(void* const* d_in, const int* in_sizes, int n_in,
                              void* d_out, int out_size) {
    const float* x    = (const float*)d_in[0];   // (32,2048,256)
    const float* h0   = (const float*)d_in[1];   // (1,32,256)
    const float* c0   = (const float*)d_in[2];   // (1,32,256)
    const float* W    = (const float*)d_in[3];   // (512,1024)
    const float* bias = (const float*)d_in[4];   // (1024,)
    float* out = (float*)d_out;                  // (32,2048,256) + 2*(1,32,256) zeros

    gemm_x_kernel<<<dim3(512, 8, 1), 256>>>(x, W, bias);
    init_kernel<<<16, 256>>>(out);
    lstm_rec_kernel<<<GRID_REC, 256>>>(W, h0, c0, out);
}